// round 3
// baseline (speedup 1.0000x reference)
#include <cuda_runtime.h>
#include <math.h>

#define T_  4096
#define D_  1024
#define S_  4
#define TB_ 1024
#define WB_ 256
#define NB_ 16

#define BM 64
#define BN 64
#define BK 16

// ---------------- scratch (static device globals; no allocation) -------------
__device__ float g_xu[T_ * D_];              // 16 MB
__device__ float g_div[S_][TB_ * TB_];       // 16 MB (diag blocks only)
__device__ float g_Q[T_ * D_];               // 16 MB
__device__ float g_K[T_ * D_];               // 16 MB
__device__ float g_V[T_ * D_];               // 16 MB
__device__ float g_AP[TB_ * TB_];            //  4 MB
__device__ float g_attw[NB_][TB_ * TB_];     // 64 MB (sim, overwritten by attw)
__device__ float g_ent[NB_][TB_];
__device__ float g_dep[NB_][TB_];
__device__ float g_ctx[NB_][TB_ * WB_];      // 16 MB
__device__ float g_y[T_ * D_];               // 16 MB
__device__ float g_W2[WB_ * WB_];            // repacked Wout2[:, :WB]
__device__ float g_w2e[WB_];                 // Wout2[:, WB]   (ent column)
__device__ float g_w2d[WB_];                 // Wout2[:, WB+1] (dep column)

// ---------------- reductions -------------------------------------------------
__device__ __forceinline__ float warpSum(float v) {
    #pragma unroll
    for (int o = 16; o; o >>= 1) v += __shfl_xor_sync(0xffffffffu, v, o);
    return v;
}
__device__ __forceinline__ float warpMax(float v) {
    #pragma unroll
    for (int o = 16; o; o >>= 1) v = fmaxf(v, __shfl_xor_sync(0xffffffffu, v, o));
    return v;
}

template <bool ISMAX>
__device__ __forceinline__ float blockReduce(float v) {
    __shared__ float sh[8];
    int lane = threadIdx.x & 31, w = threadIdx.x >> 5;
    v = ISMAX ? warpMax(v) : warpSum(v);
    if (lane == 0) sh[w] = v;
    __syncthreads();
    if (w == 0) {
        float t = (lane < 8) ? sh[lane] : (ISMAX ? -INFINITY : 0.0f);
        t = ISMAX ? warpMax(t) : warpSum(t);
        if (lane == 0) sh[0] = t;
    }
    __syncthreads();
    float r = sh[0];
    __syncthreads();
    return r;
}

// ---------------- tiled GEMM cores (64x64x16, 256 thr, 4x4/thread) -----------
// NT: acc[r][c] += sum_k A[(ty*4+r)*lda + k] * B[(tx*4+c)*ldb + k]
__device__ __forceinline__ void nt_core(const float* __restrict__ A,
                                        const float* __restrict__ B,
                                        int lda, int ldb, int K,
                                        float acc[4][4]) {
    __shared__ __align__(16) float As[BK][BM + 4];
    __shared__ __align__(16) float Bs[BK][BN + 4];
    const int tid = threadIdx.x;
    const int tx = tid & 15, ty = tid >> 4;
    const int lr = tid >> 2;            // 0..63 row being loaded
    const int lc = (tid & 3) << 2;      // 0,4,8,12 k-offset (float4)
    for (int k0 = 0; k0 < K; k0 += BK) {
        float4 a = *(const float4*)(A + (size_t)lr * lda + (k0 + lc));
        float4 b = *(const float4*)(B + (size_t)lr * ldb + (k0 + lc));
        if (k0) __syncthreads();
        As[lc + 0][lr] = a.x; As[lc + 1][lr] = a.y;
        As[lc + 2][lr] = a.z; As[lc + 3][lr] = a.w;
        Bs[lc + 0][lr] = b.x; Bs[lc + 1][lr] = b.y;
        Bs[lc + 2][lr] = b.z; Bs[lc + 3][lr] = b.w;
        __syncthreads();
        #pragma unroll
        for (int kk = 0; kk < BK; kk++) {
            float4 av = *(const float4*)(&As[kk][ty << 2]);
            float4 bv = *(const float4*)(&Bs[kk][tx << 2]);
            float ar[4] = {av.x, av.y, av.z, av.w};
            float br[4] = {bv.x, bv.y, bv.z, bv.w};
            #pragma unroll
            for (int r = 0; r < 4; r++)
                #pragma unroll
                for (int c = 0; c < 4; c++)
                    acc[r][c] += ar[r] * br[c];
        }
    }
}

// NN with per-k row scale (1+dep[k]):
// acc[r][c] += sum_k A[(ty*4+r)*lda + k] * (1+dep[k]) * B[k*ldb + (tx*4+c)]
__device__ __forceinline__ void nn_core_dep(const float* __restrict__ A,
                                            const float* __restrict__ B,
                                            const float* __restrict__ dep,
                                            int lda, int ldb, int K,
                                            float acc[4][4]) {
    __shared__ __align__(16) float As[BK][BM + 4];
    __shared__ __align__(16) float Bs[BK][BN + 4];
    const int tid = threadIdx.x;
    const int tx = tid & 15, ty = tid >> 4;
    const int lr = tid >> 2;
    const int lc = (tid & 3) << 2;
    const int bkr = tid >> 4;           // 0..15 k-row being loaded
    const int bnc = (tid & 15) << 2;    // 0..60 n-offset (float4)
    for (int k0 = 0; k0 < K; k0 += BK) {
        float4 a = *(const float4*)(A + (size_t)lr * lda + (k0 + lc));
        float scl = 1.0f + dep[k0 + bkr];
        float4 b = *(const float4*)(B + (size_t)(k0 + bkr) * ldb + bnc);
        if (k0) __syncthreads();
        As[lc + 0][lr] = a.x; As[lc + 1][lr] = a.y;
        As[lc + 2][lr] = a.z; As[lc + 3][lr] = a.w;
        *(float4*)(&Bs[bkr][bnc]) =
            make_float4(b.x * scl, b.y * scl, b.z * scl, b.w * scl);
        __syncthreads();
        #pragma unroll
        for (int kk = 0; kk < BK; kk++) {
            float4 av = *(const float4*)(&As[kk][ty << 2]);
            float4 bv = *(const float4*)(&Bs[kk][tx << 2]);
            float ar[4] = {av.x, av.y, av.z, av.w};
            float br[4] = {bv.x, bv.y, bv.z, bv.w};
            #pragma unroll
            for (int r = 0; r < 4; r++)
                #pragma unroll
                for (int c = 0; c < 4; c++)
                    acc[r][c] += ar[r] * br[c];
        }
    }
}

// ---------------- stage kernels ----------------------------------------------
// row L2-normalize x -> g_xu
__global__ void k_norm(const float* __restrict__ x) {
    int t = blockIdx.x, tid = threadIdx.x;
    const float* xp = x + (size_t)t * D_;
    float v = 0.0f;
    for (int j = tid; j < D_; j += 256) { float a = xp[j]; v += a * a; }
    v = blockReduce<false>(v);
    float inv = 1.0f / fmaxf(sqrtf(v), 1e-12f);
    for (int j = tid; j < D_; j += 256) g_xu[(size_t)t * D_ + j] = xp[j] * inv;
}

// absolute position matrix [TB,TB]
__global__ void k_ap() {
    int idx = blockIdx.x * 256 + threadIdx.x;      // TB*TB/256 = 4096 blocks
    int p = idx >> 10, c = idx & 1023;
    int ih = c >> 1;
    float ang = (float)p / powf(10000.0f, (2.0f * (float)ih) / 1024.0f);
    g_AP[idx] = (c & 1) ? cosf(ang) : sinf(ang);
}

// repack Wout2 [256,258] -> [256,256] + two columns
__global__ void k_repack(const float* __restrict__ W2) {
    int idx = blockIdx.x * 256 + threadIdx.x;      // 258 blocks covers 66048
    if (idx >= WB_ * (WB_ + 2)) return;
    int n = idx / (WB_ + 2), k = idx % (WB_ + 2);
    float v = W2[idx];
    if (k < WB_)            g_W2[n * WB_ + k] = v;
    else if (k == WB_)      g_w2e[n] = v;
    else                    g_w2d[n] = v;
}

// diversity diag block i: div = 1 - xu_i @ xu_i^T
__global__ void k_gemm_div() {
    int iq = blockIdx.z;
    int m0 = blockIdx.y * BM, n0 = blockIdx.x * BN;
    const float* base = g_xu + (size_t)iq * TB_ * D_;
    float acc[4][4] = {};
    nt_core(base + (size_t)m0 * D_, base + (size_t)n0 * D_, D_, D_, D_, acc);
    int tx = threadIdx.x & 15, ty = threadIdx.x >> 4;
    float* C = g_div[iq];
    #pragma unroll
    for (int r = 0; r < 4; r++)
        #pragma unroll
        for (int c = 0; c < 4; c++)
            C[(size_t)(m0 + ty * 4 + r) * TB_ + (n0 + tx * 4 + c)] = 1.0f - acc[r][c];
}

// Q/K/V = x @ W^T  (which: 0=Q,1=K,2=V)
__global__ void k_gemm_qkv(const float* __restrict__ A,
                           const float* __restrict__ W, int which) {
    int m0 = blockIdx.y * BM, n0 = blockIdx.x * BN;
    float acc[4][4] = {};
    nt_core(A + (size_t)m0 * D_, W + (size_t)n0 * D_, D_, D_, D_, acc);
    float* C = (which == 0) ? g_Q : (which == 1) ? g_K : g_V;
    int tx = threadIdx.x & 15, ty = threadIdx.x >> 4;
    #pragma unroll
    for (int r = 0; r < 4; r++)
        #pragma unroll
        for (int c = 0; c < 4; c++)
            C[(size_t)(m0 + ty * 4 + r) * D_ + (n0 + tx * 4 + c)] = acc[r][c];
}

// sim[b] = Qb @ Kb^T + AP
__global__ void k_gemm_sim() {
    int b = blockIdx.z, i = b >> 2, j = b & 3;
    int m0 = blockIdx.y * BM, n0 = blockIdx.x * BN;
    const float* Aq = g_Q + (size_t)(i * TB_ + m0) * D_ + j * WB_;
    const float* Bk = g_K + (size_t)(i * TB_ + n0) * D_ + j * WB_;
    float acc[4][4] = {};
    nt_core(Aq, Bk, D_, D_, WB_, acc);
    float* C = g_attw[b];
    int tx = threadIdx.x & 15, ty = threadIdx.x >> 4;
    #pragma unroll
    for (int r = 0; r < 4; r++)
        #pragma unroll
        for (int c = 0; c < 4; c++) {
            int m = m0 + ty * 4 + r, n = n0 + tx * 4 + c;
            C[(size_t)m * TB_ + n] = acc[r][c] + g_AP[(size_t)m * TB_ + n];
        }
}

// softmax over each row; also raw entropy + dependency
__global__ void k_softmax() {
    int row = blockIdx.x;                 // NB_*TB_ = 16384
    int b = row >> 10, q = row & 1023;
    int i = b >> 2;
    int tid = threadIdx.x;
    float* sp = g_attw[b] + (size_t)q * TB_;
    const float* dv = g_div[i] + (size_t)q * TB_;
    float s[4], d[4];
    #pragma unroll
    for (int j = 0; j < 4; j++) { s[j] = sp[tid + j * 256]; d[j] = dv[tid + j * 256]; }
    float mx = fmaxf(fmaxf(s[0], s[1]), fmaxf(s[2], s[3]));
    mx = blockReduce<true>(mx);
    float e[4], Z = 0.0f, t = 0.0f, w = 0.0f, ds = 0.0f;
    #pragma unroll
    for (int j = 0; j < 4; j++) {
        e[j] = __expf(s[j] - mx);
        Z += e[j];
        t += e[j] * (s[j] - mx);
        w += d[j] * e[j];
        ds += d[j];
    }
    Z = blockReduce<false>(Z);
    t = blockReduce<false>(t);
    w = blockReduce<false>(w);
    ds = blockReduce<false>(ds);
    float invZ = 1.0f / Z;
    #pragma unroll
    for (int j = 0; j < 4; j++) sp[tid + j * 256] = e[j] * invZ;
    if (tid == 0) {
        // ent = (logZ - t/Z)/ln(TB);  dep = (w/Z)/ds
        g_ent[b][q] = (logf(Z) - t * invZ) * (1.0f / 6.931471805599453f);
        g_dep[b][q] = (w * invZ) / ds;
    }
}

// L1-normalize ent per block
__global__ void k_entnorm() {
    int b = blockIdx.x, tid = threadIdx.x;
    float v = 0.0f;
    for (int j = tid; j < TB_; j += 256) v += fabsf(g_ent[b][j]);
    v = blockReduce<false>(v);
    float inv = 1.0f / fmaxf(v, 1e-12f);
    for (int j = tid; j < TB_; j += 256) g_ent[b][j] *= inv;
}

// ctx[b] = attw[b] @ diag(1+dep[b]) @ Vb
__global__ void k_gemm_ctx() {
    int b = blockIdx.z, i = b >> 2, j = b & 3;
    int m0 = blockIdx.y * BM, n0 = blockIdx.x * BN;   // grid.x = WB/BN = 4
    const float* A = g_attw[b] + (size_t)m0 * TB_;
    const float* B = g_V + (size_t)(i * TB_) * D_ + j * WB_ + n0;
    float acc[4][4] = {};
    nn_core_dep(A, B, g_dep[b], TB_, D_, TB_, acc);
    float* C = g_ctx[b];
    int tx = threadIdx.x & 15, ty = threadIdx.x >> 4;
    #pragma unroll
    for (int r = 0; r < 4; r++)
        #pragma unroll
        for (int c = 0; c < 4; c++)
            C[(size_t)(m0 + ty * 4 + r) * WB_ + (n0 + tx * 4 + c)] = acc[r][c];
}

// y_block = ctx @ W2^T + ent*w2e + dep*w2d, scattered into g_y grid layout
__global__ void k_gemm_out2() {
    int b = blockIdx.z, i = b >> 2, j = b & 3;
    int m0 = blockIdx.y * BM, n0 = blockIdx.x * BN;   // grid (4,16)
    float acc[4][4] = {};
    nt_core(g_ctx[b] + (size_t)m0 * WB_, g_W2 + (size_t)n0 * WB_, WB_, WB_, WB_, acc);
    int tx = threadIdx.x & 15, ty = threadIdx.x >> 4;
    #pragma unroll
    for (int r = 0; r < 4; r++)
        #pragma unroll
        for (int c = 0; c < 4; c++) {
            int q = m0 + ty * 4 + r, n = n0 + tx * 4 + c;
            float v = acc[r][c] + g_ent[b][q] * g_w2e[n] + g_dep[b][q] * g_w2d[n];
            g_y[(size_t)(i * TB_ + q) * D_ + (j * WB_ + n)] = v;
        }
}

// out = y @ Wout^T
__global__ void k_gemm_final(const float* __restrict__ Wout, float* __restrict__ out) {
    int m0 = blockIdx.y * BM, n0 = blockIdx.x * BN;
    float acc[4][4] = {};
    nt_core(g_y + (size_t)m0 * D_, Wout + (size_t)n0 * D_, D_, D_, D_, acc);
    int tx = threadIdx.x & 15, ty = threadIdx.x >> 4;
    #pragma unroll
    for (int r = 0; r < 4; r++)
        #pragma unroll
        for (int c = 0; c < 4; c++)
            out[(size_t)(m0 + ty * 4 + r) * D_ + (n0 + tx * 4 + c)] = acc[r][c];
}

// ---------------- launch -----------------------------------------------------
extern "C" void kernel_launch(void* const* d_in, const int* in_sizes, int n_in,
                              void* d_out, int out_size) {
    const float* x    = (const float*)d_in[0];
    const float* Wq   = (const float*)d_in[1];
    const float* Wk   = (const float*)d_in[2];
    const float* Wv   = (const float*)d_in[3];
    const float* Wout = (const float*)d_in[4];
    const float* W2   = (const float*)d_in[5];
    float* out = (float*)d_out;

    k_norm<<<T_, 256>>>(x);
    k_ap<<<(TB_ * TB_) / 256, 256>>>();
    k_repack<<<(WB_ * (WB_ + 2) + 255) / 256, 256>>>(W2);

    k_gemm_div<<<dim3(TB_ / BN, TB_ / BM, S_), 256>>>();

    k_gemm_qkv<<<dim3(D_ / BN, T_ / BM), 256>>>(x, Wq, 0);
    k_gemm_qkv<<<dim3(D_ / BN, T_ / BM), 256>>>(x, Wk, 1);
    k_gemm_qkv<<<dim3(D_ / BN, T_ / BM), 256>>>(x, Wv, 2);

    k_gemm_sim<<<dim3(TB_ / BN, TB_ / BM, NB_), 256>>>();
    k_softmax<<<NB_ * TB_, 256>>>();
    k_entnorm<<<NB_, 256>>>();
    k_gemm_ctx<<<dim3(WB_ / BN, TB_ / BM, NB_), 256>>>();
    k_gemm_out2<<<dim3(WB_ / BN, TB_ / BM, NB_), 256>>>();
    k_gemm_final<<<dim3(D_ / BN, T_ / BM), 256>>>(Wout, out);
}

// round 7
// speedup vs baseline: 1.4308x; 1.4308x over previous
#include <cuda_runtime.h>
#include <math.h>
#include <stdint.h>

#define T_  4096
#define D_  1024
#define S_  4
#define TB_ 1024
#define WB_ 256
#define NB_ 16

#define MT 128
#define NT 128
#define KC 32
#define THREADS 256
#define STRD 36                        // padded row stride (floats)
#define STG  (128 * STRD)              // floats per tile stage buffer
#define SMEM_DYN (4 * STG * 4)         // 2 stages x (A+B), bytes = 73728

// ---------------- scratch (static device globals; no allocation) -------------
__device__ float g_xu[T_ * D_];
__device__ float g_div[S_][TB_ * TB_];
__device__ float g_Q[T_ * D_];
__device__ float g_K[T_ * D_];
__device__ float g_V[T_ * D_];
__device__ float g_Vt[NB_][WB_ * TB_];   // V block transposed [n][k], (1+dep) folded
__device__ float g_AP[TB_ * TB_];
__device__ float g_attw[NB_][TB_ * TB_];
__device__ float g_ent[NB_][TB_];
__device__ float g_dep[NB_][TB_];
__device__ float g_ctx[NB_][TB_ * WB_];
__device__ float g_y[T_ * D_];
__device__ float g_W2[WB_ * WB_];
__device__ float g_w2e[WB_];
__device__ float g_w2d[WB_];

// ---------------- helpers ----------------------------------------------------
__device__ __forceinline__ uint32_t tf32r(float x) {
    uint32_t u;
    asm("cvt.rna.tf32.f32 %0, %1;" : "=r"(u) : "f"(x));
    return u;
}
// split x into hi (tf32) + lo (tf32 of residual)
__device__ __forceinline__ void tf32split(float x, uint32_t& hi, uint32_t& lo) {
    hi = tf32r(x);
    lo = tf32r(x - __uint_as_float(hi));
}

__device__ __forceinline__ void mma_tf32(float c[4], const uint32_t a[4],
                                         const uint32_t b[2]) {
    asm volatile(
        "mma.sync.aligned.m16n8k8.row.col.f32.tf32.tf32.f32 "
        "{%0,%1,%2,%3}, {%4,%5,%6,%7}, {%8,%9}, {%0,%1,%2,%3};"
        : "+f"(c[0]), "+f"(c[1]), "+f"(c[2]), "+f"(c[3])
        : "r"(a[0]), "r"(a[1]), "r"(a[2]), "r"(a[3]), "r"(b[0]), "r"(b[1]));
}

__device__ __forceinline__ float warpSum(float v) {
    #pragma unroll
    for (int o = 16; o; o >>= 1) v += __shfl_xor_sync(0xffffffffu, v, o);
    return v;
}
__device__ __forceinline__ float warpMax(float v) {
    #pragma unroll
    for (int o = 16; o; o >>= 1) v = fmaxf(v, __shfl_xor_sync(0xffffffffu, v, o));
    return v;
}
template <bool ISMAX>
__device__ __forceinline__ float blockReduce(float v) {
    __shared__ float sh[8];
    int lane = threadIdx.x & 31, w = threadIdx.x >> 5;
    v = ISMAX ? warpMax(v) : warpSum(v);
    if (lane == 0) sh[w] = v;
    __syncthreads();
    if (w == 0) {
        float t = (lane < 8) ? sh[lane] : (ISMAX ? -INFINITY : 0.0f);
        t = ISMAX ? warpMax(t) : warpSum(t);
        if (lane == 0) sh[0] = t;
    }
    __syncthreads();
    float r = sh[0];
    __syncthreads();
    return r;
}

// ------------- 3xTF32 mma.sync GEMM (NT, 128x128 CTA, 64x32 warp) ------------
enum { M_DIV = 0, M_Q = 1, M_K = 2, M_V = 3, M_SIM = 4, M_CTX = 5, M_OUT2 = 6, M_FIN = 7 };

__global__ void __launch_bounds__(THREADS, 1)
k_mma(int mode, const float* __restrict__ pA, const float* __restrict__ pB,
      float* __restrict__ pC) {
    extern __shared__ float sm[];
    const int tid = threadIdx.x, w = tid >> 5, lane = tid & 31;
    const int wr = w >> 2, wc = w & 3;              // warp grid 2x4
    const int gid = lane >> 2, t4 = lane & 3;       // mma fragment coords

    // ---- per-mode problem setup ----
    const float *A, *B;
    float* C = nullptr;
    int K, lda, ldb, ldc = 0;
    const int z = blockIdx.z, bi = z >> 2, bj = z & 3;
    switch (mode) {
        case M_DIV:
            A = g_xu + (size_t)z * TB_ * D_; B = A;
            C = g_div[z]; K = D_; lda = ldb = D_; ldc = TB_; break;
        case M_Q: case M_K: case M_V:
            A = pA; B = pB;
            C = (mode == M_Q) ? g_Q : (mode == M_K) ? g_K : g_V;
            K = D_; lda = ldb = D_; ldc = D_; break;
        case M_SIM:
            A = g_Q + (size_t)(bi * TB_) * D_ + bj * WB_;
            B = g_K + (size_t)(bi * TB_) * D_ + bj * WB_;
            C = g_attw[z]; K = WB_; lda = ldb = D_; ldc = TB_; break;
        case M_CTX:
            A = g_attw[z]; B = g_Vt[z];
            C = g_ctx[z]; K = TB_; lda = TB_; ldb = TB_; ldc = WB_; break;
        case M_OUT2:
            A = g_ctx[z]; B = g_W2;
            K = WB_; lda = WB_; ldb = WB_; break;
        default: // M_FIN
            A = g_y; B = pB; C = pC; K = D_; lda = ldb = D_; ldc = D_; break;
    }
    const int m0 = blockIdx.y * MT, n0 = blockIdx.x * NT;
    A += (size_t)m0 * lda;
    B += (size_t)n0 * ldb;

    // ---- load mapping: 4 float4 per operand per chunk per thread ----
    const float* pa[4];
    const float* pb[4];
    int soff[4];
    #pragma unroll
    for (int p = 0; p < 4; p++) {
        int pos = tid + p * THREADS;        // 0..1023
        int r = pos >> 3, c4 = (pos & 7) << 2;
        soff[p] = r * STRD + c4;
        pa[p] = A + (size_t)r * lda + c4;
        pb[p] = B + (size_t)r * ldb + c4;
    }

    float acc[4][4][4] = {};
    const int nChunks = K / KC;

    float4 ra[4], rb[4];
    #pragma unroll
    for (int p = 0; p < 4; p++) { ra[p] = *(const float4*)(pa[p]); rb[p] = *(const float4*)(pb[p]); }

    // store stage 0 (raw fp32; split happens at fragment load)
    {
        float* As = sm; float* Bs = sm + STG;
        #pragma unroll
        for (int p = 0; p < 4; p++) {
            *(float4*)(As + soff[p]) = ra[p];
            *(float4*)(Bs + soff[p]) = rb[p];
        }
    }
    __syncthreads();

    for (int ch = 0; ch < nChunks; ch++) {
        if (ch + 1 < nChunks) {
            #pragma unroll
            for (int p = 0; p < 4; p++) {
                ra[p] = *(const float4*)(pa[p] + (ch + 1) * KC);
                rb[p] = *(const float4*)(pb[p] + (ch + 1) * KC);
            }
        }
        // compute from stage ch&1
        {
            const float* As = sm + (ch & 1) * (2 * STG);
            const float* Bs = As + STG;
            #pragma unroll
            for (int kk = 0; kk < KC; kk += 8) {
                uint32_t ah[4][4], al[4][4], bh[4][2], bl[4][2];
                const int c0 = kk + t4, c1 = kk + t4 + 4;
                #pragma unroll
                for (int mi = 0; mi < 4; mi++) {
                    const int r0 = wr * 64 + mi * 16 + gid;
                    tf32split(As[r0 * STRD + c0],       ah[mi][0], al[mi][0]);
                    tf32split(As[(r0 + 8) * STRD + c0], ah[mi][1], al[mi][1]);
                    tf32split(As[r0 * STRD + c1],       ah[mi][2], al[mi][2]);
                    tf32split(As[(r0 + 8) * STRD + c1], ah[mi][3], al[mi][3]);
                }
                #pragma unroll
                for (int ni = 0; ni < 4; ni++) {
                    const int nr = wc * 32 + ni * 8 + gid;
                    tf32split(Bs[nr * STRD + c0], bh[ni][0], bl[ni][0]);
                    tf32split(Bs[nr * STRD + c1], bh[ni][1], bl[ni][1]);
                }
                #pragma unroll
                for (int mi = 0; mi < 4; mi++)
                    #pragma unroll
                    for (int ni = 0; ni < 4; ni++) {
                        mma_tf32(acc[mi][ni], ah[mi], bl[ni]);   // hi*lo
                        mma_tf32(acc[mi][ni], al[mi], bh[ni]);   // lo*hi
                        mma_tf32(acc[mi][ni], ah[mi], bh[ni]);   // hi*hi
                    }
            }
        }
        if (ch + 1 < nChunks) {
            float* As = sm + ((ch + 1) & 1) * (2 * STG);
            float* Bs = As + STG;
            #pragma unroll
            for (int p = 0; p < 4; p++) {
                *(float4*)(As + soff[p]) = ra[p];
                *(float4*)(Bs + soff[p]) = rb[p];
            }
            __syncthreads();
        }
    }

    // ---- epilogue: fragment (mi,ni) -> rows mr0/mr0+8, cols nc..nc+1 --------
    #pragma unroll
    for (int mi = 0; mi < 4; mi++) {
        const int mr0 = m0 + wr * 64 + mi * 16 + gid;
        const int mr1 = mr0 + 8;
        float e0 = 0.f, e1 = 0.f, d0 = 0.f, d1 = 0.f;
        if (mode == M_OUT2) {
            e0 = g_ent[z][mr0]; e1 = g_ent[z][mr1];
            d0 = g_dep[z][mr0]; d1 = g_dep[z][mr1];
        }
        #pragma unroll
        for (int ni = 0; ni < 4; ni++) {
            const int nc = n0 + wc * 32 + ni * 8 + 2 * t4;
            float v00 = acc[mi][ni][0], v01 = acc[mi][ni][1];
            float v10 = acc[mi][ni][2], v11 = acc[mi][ni][3];
            if (mode == M_DIV) {
                v00 = 1.0f - v00; v01 = 1.0f - v01;
                v10 = 1.0f - v10; v11 = 1.0f - v11;
            } else if (mode == M_SIM) {
                v00 += g_AP[(size_t)mr0 * TB_ + nc];
                v01 += g_AP[(size_t)mr0 * TB_ + nc + 1];
                v10 += g_AP[(size_t)mr1 * TB_ + nc];
                v11 += g_AP[(size_t)mr1 * TB_ + nc + 1];
            }
            if (mode == M_OUT2) {
                const float we0 = g_w2e[nc], we1 = g_w2e[nc + 1];
                const float wd0 = g_w2d[nc], wd1 = g_w2d[nc + 1];
                float* y0 = g_y + (size_t)(bi * TB_ + mr0) * D_ + bj * WB_ + nc;
                float* y1 = g_y + (size_t)(bi * TB_ + mr1) * D_ + bj * WB_ + nc;
                y0[0] = v00 + e0 * we0 + d0 * wd0;
                y0[1] = v01 + e0 * we1 + d0 * wd1;
                y1[0] = v10 + e1 * we0 + d1 * wd0;
                y1[1] = v11 + e1 * we1 + d1 * wd1;
            } else {
                float* c0p = C + (size_t)mr0 * ldc + nc;
                float* c1p = C + (size_t)mr1 * ldc + nc;
                *(float2*)c0p = make_float2(v00, v01);
                *(float2*)c1p = make_float2(v10, v11);
            }
        }
    }
}

// ---------------- elementwise stage kernels ----------------------------------
__global__ void k_norm(const float* __restrict__ x) {
    int t = blockIdx.x, tid = threadIdx.x;
    const float* xp = x + (size_t)t * D_;
    float v = 0.0f;
    for (int j = tid; j < D_; j += 256) { float a = xp[j]; v += a * a; }
    v = blockReduce<false>(v);
    float inv = 1.0f / fmaxf(sqrtf(v), 1e-12f);
    for (int j = tid; j < D_; j += 256) g_xu[(size_t)t * D_ + j] = xp[j] * inv;
}

__global__ void k_ap() {
    int idx = blockIdx.x * 256 + threadIdx.x;
    int p = idx >> 10, c = idx & 1023;
    int ih = c >> 1;
    float ang = (float)p / powf(10000.0f, (2.0f * (float)ih) / 1024.0f);
    g_AP[idx] = (c & 1) ? cosf(ang) : sinf(ang);
}

__global__ void k_repack(const float* __restrict__ W2) {
    int idx = blockIdx.x * 256 + threadIdx.x;
    if (idx >= WB_ * (WB_ + 2)) return;
    int n = idx / (WB_ + 2), k = idx % (WB_ + 2);
    float v = W2[idx];
    if (k < WB_)       g_W2[n * WB_ + k] = v;
    else if (k == WB_) g_w2e[n] = v;
    else               g_w2d[n] = v;
}

__global__ void k_softmax() {
    int row = blockIdx.x;
    int b = row >> 10, q = row & 1023;
    int i = b >> 2;
    int tid = threadIdx.x;
    float* sp = g_attw[b] + (size_t)q * TB_;
    const float* dv = g_div[i] + (size_t)q * TB_;
    float s[4], d[4];
    #pragma unroll
    for (int j = 0; j < 4; j++) { s[j] = sp[tid + j * 256]; d[j] = dv[tid + j * 256]; }
    float mx = fmaxf(fmaxf(s[0], s[1]), fmaxf(s[2], s[3]));
    mx = blockReduce<true>(mx);
    float e[4], Z = 0.0f, t = 0.0f, ww = 0.0f, ds = 0.0f;
    #pragma unroll
    for (int j = 0; j < 4; j++) {
        e[j] = __expf(s[j] - mx);
        Z += e[j]; t += e[j] * (s[j] - mx); ww += d[j] * e[j]; ds += d[j];
    }
    Z = blockReduce<false>(Z);
    t = blockReduce<false>(t);
    ww = blockReduce<false>(ww);
    ds = blockReduce<false>(ds);
    float invZ = 1.0f / Z;
    #pragma unroll
    for (int j = 0; j < 4; j++) sp[tid + j * 256] = e[j] * invZ;
    if (tid == 0) {
        g_ent[b][q] = (logf(Z) - t * invZ) * (1.0f / 6.931471805599453f);
        g_dep[b][q] = (ww * invZ) / ds;
    }
}

__global__ void k_entnorm() {
    int b = blockIdx.x, tid = threadIdx.x;
    float v = 0.0f;
    for (int j = tid; j < TB_; j += 256) v += fabsf(g_ent[b][j]);
    v = blockReduce<false>(v);
    float inv = 1.0f / fmaxf(v, 1e-12f);
    for (int j = tid; j < TB_; j += 256) g_ent[b][j] *= inv;
}

// Vt[b][n][k] = V[(i*TB+k)*D + j*WB+n] * (1 + dep[b][k])
__global__ void k_vt() {
    __shared__ float tile[32][33];
    int b = blockIdx.z, i = b >> 2, j = b & 3;
    int k0 = blockIdx.x * 32, n0 = blockIdx.y * 32;
    int tx = threadIdx.x, ty = threadIdx.y;    // 32 x 8
    #pragma unroll
    for (int dy = 0; dy < 4; dy++) {
        int k = k0 + ty + dy * 8;
        int n = n0 + tx;
        tile[ty + dy * 8][tx] =
            g_V[(size_t)(i * TB_ + k) * D_ + j * WB_ + n] * (1.0f + g_dep[b][k]);
    }
    __syncthreads();
    #pragma unroll
    for (int dy = 0; dy < 4; dy++) {
        int n = n0 + ty + dy * 8;
        int k = k0 + tx;
        g_Vt[b][(size_t)n * TB_ + k] = tile[tx][ty + dy * 8];
    }
}

// ---------------- launch -----------------------------------------------------
extern "C" void kernel_launch(void* const* d_in, const int* in_sizes, int n_in,
                              void* d_out, int out_size) {
    const float* x    = (const float*)d_in[0];
    const float* Wq   = (const float*)d_in[1];
    const float* Wk   = (const float*)d_in[2];
    const float* Wv   = (const float*)d_in[3];
    const float* Wout = (const float*)d_in[4];
    const float* W2   = (const float*)d_in[5];
    float* out = (float*)d_out;

    cudaFuncSetAttribute(k_mma, cudaFuncAttributeMaxDynamicSharedMemorySize, SMEM_DYN);

    k_norm<<<T_, 256>>>(x);
    k_ap<<<(TB_ * TB_) / 256, 256>>>();
    k_repack<<<(WB_ * (WB_ + 2) + 255) / 256, 256>>>(W2);

    k_mma<<<dim3(TB_ / NT, TB_ / MT, S_), THREADS, SMEM_DYN>>>(M_DIV, nullptr, nullptr, nullptr);

    k_mma<<<dim3(D_ / NT, T_ / MT, 1), THREADS, SMEM_DYN>>>(M_Q, x, Wq, nullptr);
    k_mma<<<dim3(D_ / NT, T_ / MT, 1), THREADS, SMEM_DYN>>>(M_K, x, Wk, nullptr);
    k_mma<<<dim3(D_ / NT, T_ / MT, 1), THREADS, SMEM_DYN>>>(M_V, x, Wv, nullptr);

    k_mma<<<dim3(TB_ / NT, TB_ / MT, NB_), THREADS, SMEM_DYN>>>(M_SIM, nullptr, nullptr, nullptr);

    k_softmax<<<NB_ * TB_, 256>>>();
    k_entnorm<<<NB_, 256>>>();
    k_vt<<<dim3(TB_ / 32, WB_ / 32, NB_), dim3(32, 8)>>>();

    k_mma<<<dim3(WB_ / NT, TB_ / MT, NB_), THREADS, SMEM_DYN>>>(M_CTX, nullptr, nullptr, nullptr);
    k_mma<<<dim3(WB_ / NT, TB_ / MT, NB_), THREADS, SMEM_DYN>>>(M_OUT2, nullptr, nullptr, nullptr);
    k_mma<<<dim3(D_ / NT, T_ / MT, 1), THREADS, SMEM_DYN>>>(M_FIN, nullptr, Wout, out);
}

// round 10
// speedup vs baseline: 2.4503x; 1.7125x over previous
#include <cuda_runtime.h>
#include <math.h>
#include <stdint.h>

#define T_  4096
#define D_  1024
#define S_  4
#define TB_ 1024
#define WB_ 256
#define NB_ 16

#define MT 128
#define NT 128
#define KC 32
#define THREADS 256
#define TW 20                      // smem words per row (16 data + 4 pad)
#define TILEW (128 * TW)           // 2560 words per tile
#define STAGEW (4 * TILEW)         // Ah, Al, Bh, Bl
#define SMEM_DYN (2 * STAGEW * 4)  // 81920 bytes

// ---------------- scratch (identical to R7 passing kernel) -------------------
__device__ float g_xu[T_ * D_];
__device__ float g_div[S_][TB_ * TB_];
__device__ float g_Q[T_ * D_];
__device__ float g_K[T_ * D_];
__device__ float g_V[T_ * D_];
__device__ float g_Vt[NB_][WB_ * TB_];   // V block transposed [n][k], (1+dep) folded
__device__ float g_AP[TB_ * TB_];
__device__ float g_attw[NB_][TB_ * TB_];
__device__ float g_ent[NB_][TB_];
__device__ float g_dep[NB_][TB_];
__device__ float g_ctx[NB_][TB_ * WB_];
__device__ float g_y[T_ * D_];
__device__ float g_W2[WB_ * WB_];
__device__ float g_w2e[WB_];
__device__ float g_w2d[WB_];

// ---------------- helpers ----------------------------------------------------
// split pair (x0,x1) -> packed bf16x2 hi word + lo (residual) word
__device__ __forceinline__ void bsplit(float x0, float x1, uint32_t& hi, uint32_t& lo) {
    uint32_t h;
    asm("cvt.rn.bf16x2.f32 %0, %1, %2;" : "=r"(h) : "f"(x1), "f"(x0));
    float f0 = __uint_as_float(h << 16);
    float f1 = __uint_as_float(h & 0xFFFF0000u);
    float r0 = x0 - f0, r1 = x1 - f1;
    uint32_t l;
    asm("cvt.rn.bf16x2.f32 %0, %1, %2;" : "=r"(l) : "f"(r1), "f"(r0));
    hi = h; lo = l;
}

__device__ __forceinline__ void mma_bf16(float c[4], const uint32_t a[4],
                                         const uint32_t b[2]) {
    asm volatile(
        "mma.sync.aligned.m16n8k16.row.col.f32.bf16.bf16.f32 "
        "{%0,%1,%2,%3}, {%4,%5,%6,%7}, {%8,%9}, {%0,%1,%2,%3};"
        : "+f"(c[0]), "+f"(c[1]), "+f"(c[2]), "+f"(c[3])
        : "r"(a[0]), "r"(a[1]), "r"(a[2]), "r"(a[3]), "r"(b[0]), "r"(b[1]));
}

__device__ __forceinline__ float warpSum(float v) {
    #pragma unroll
    for (int o = 16; o; o >>= 1) v += __shfl_xor_sync(0xffffffffu, v, o);
    return v;
}
__device__ __forceinline__ float warpMax(float v) {
    #pragma unroll
    for (int o = 16; o; o >>= 1) v = fmaxf(v, __shfl_xor_sync(0xffffffffu, v, o));
    return v;
}
template <bool ISMAX>
__device__ __forceinline__ float blockReduce(float v) {
    __shared__ float sh[8];
    int lane = threadIdx.x & 31, w = threadIdx.x >> 5;
    v = ISMAX ? warpMax(v) : warpSum(v);
    if (lane == 0) sh[w] = v;
    __syncthreads();
    if (w == 0) {
        float t = (lane < 8) ? sh[lane] : (ISMAX ? -INFINITY : 0.0f);
        t = ISMAX ? warpMax(t) : warpSum(t);
        if (lane == 0) sh[0] = t;
    }
    __syncthreads();
    float r = sh[0];
    __syncthreads();
    return r;
}

// ------- bf16x3 mma.sync GEMM, fp32 in/out (NT, 128x128 CTA, 64x32 warp) -----
enum { M_DIV = 0, M_Q = 1, M_K = 2, M_V = 3, M_SIM = 4, M_CTX = 5, M_OUT2 = 6, M_FIN = 7 };

__global__ void __launch_bounds__(THREADS, 1)
k_mma(int mode, const float* __restrict__ pA, const float* __restrict__ pB,
      float* __restrict__ pC) {
    extern __shared__ uint32_t sm[];
    const int tid = threadIdx.x, w = tid >> 5, lane = tid & 31;
    const int wr = w >> 2, wc = w & 3;              // warp grid 2x4
    const int gid = lane >> 2, t4 = lane & 3;       // fragment coords

    // ---- per-mode problem setup (identical to R7) ----
    const float *A, *B;
    float* C = nullptr;
    int K, lda, ldb, ldc = 0;
    const int z = blockIdx.z, bi = z >> 2, bj = z & 3;
    switch (mode) {
        case M_DIV:
            A = g_xu + (size_t)z * TB_ * D_; B = A;
            C = g_div[z]; K = D_; lda = ldb = D_; ldc = TB_; break;
        case M_Q: case M_K: case M_V:
            A = pA; B = pB;
            C = (mode == M_Q) ? g_Q : (mode == M_K) ? g_K : g_V;
            K = D_; lda = ldb = D_; ldc = D_; break;
        case M_SIM:
            A = g_Q + (size_t)(bi * TB_) * D_ + bj * WB_;
            B = g_K + (size_t)(bi * TB_) * D_ + bj * WB_;
            C = g_attw[z]; K = WB_; lda = ldb = D_; ldc = TB_; break;
        case M_CTX:
            A = g_attw[z]; B = g_Vt[z];
            C = g_ctx[z]; K = TB_; lda = TB_; ldb = TB_; ldc = WB_; break;
        case M_OUT2:
            A = g_ctx[z]; B = g_W2;
            K = WB_; lda = WB_; ldb = WB_; break;
        default: // M_FIN
            A = g_y; B = pB; C = pC; K = D_; lda = ldb = D_; ldc = D_; break;
    }
    const int m0 = blockIdx.y * MT, n0 = blockIdx.x * NT;
    A += (size_t)m0 * lda;
    B += (size_t)n0 * ldb;

    // ---- loader mapping: 4 float4 per operand per chunk (as R7) ----
    const float* pa[4];
    const float* pb[4];
    int soff[4];
    #pragma unroll
    for (int p = 0; p < 4; p++) {
        int pos = tid + p * THREADS;        // 0..1023
        int r = pos >> 3, c4 = (pos & 7) << 2;
        soff[p] = r * TW + (c4 >> 1);       // word offset (even)
        pa[p] = A + (size_t)r * lda + c4;
        pb[p] = B + (size_t)r * ldb + c4;
    }

    float acc[4][4][4] = {};
    const int nChunks = K / KC;

    float4 ra[4], rb[4];
    #pragma unroll
    for (int p = 0; p < 4; p++) { ra[p] = *(const float4*)(pa[p]); rb[p] = *(const float4*)(pb[p]); }

    // split + store stage 0
    {
        uint32_t* b0 = sm;
        #pragma unroll
        for (int p = 0; p < 4; p++) {
            uint32_t h0, l0, h1, l1;
            bsplit(ra[p].x, ra[p].y, h0, l0);
            bsplit(ra[p].z, ra[p].w, h1, l1);
            *(uint2*)(b0 + soff[p])          = make_uint2(h0, h1);
            *(uint2*)(b0 + TILEW + soff[p])  = make_uint2(l0, l1);
            bsplit(rb[p].x, rb[p].y, h0, l0);
            bsplit(rb[p].z, rb[p].w, h1, l1);
            *(uint2*)(b0 + 2 * TILEW + soff[p]) = make_uint2(h0, h1);
            *(uint2*)(b0 + 3 * TILEW + soff[p]) = make_uint2(l0, l1);
        }
    }
    __syncthreads();

    for (int ch = 0; ch < nChunks; ch++) {
        if (ch + 1 < nChunks) {
            #pragma unroll
            for (int p = 0; p < 4; p++) {
                ra[p] = *(const float4*)(pa[p] + (ch + 1) * KC);
                rb[p] = *(const float4*)(pb[p] + (ch + 1) * KC);
            }
        }
        // compute from stage ch&1
        {
            const uint32_t* base = sm + (ch & 1) * STAGEW;
            const uint32_t* Ahs = base;
            const uint32_t* Als = base + TILEW;
            const uint32_t* Bhs = base + 2 * TILEW;
            const uint32_t* Bls = base + 3 * TILEW;
            #pragma unroll
            for (int s16 = 0; s16 < 2; s16++) {
                const int w0 = s16 * 8 + t4, w1 = w0 + 4;
                uint32_t ah[4][4], al[4][4], bh[4][2], bl[4][2];
                #pragma unroll
                for (int mi = 0; mi < 4; mi++) {
                    const int r0 = (wr * 64 + mi * 16 + gid) * TW;
                    const int r8 = r0 + 8 * TW;
                    ah[mi][0] = Ahs[r0 + w0]; ah[mi][1] = Ahs[r8 + w0];
                    ah[mi][2] = Ahs[r0 + w1]; ah[mi][3] = Ahs[r8 + w1];
                    al[mi][0] = Als[r0 + w0]; al[mi][1] = Als[r8 + w0];
                    al[mi][2] = Als[r0 + w1]; al[mi][3] = Als[r8 + w1];
                }
                #pragma unroll
                for (int ni = 0; ni < 4; ni++) {
                    const int nr = (wc * 32 + ni * 8 + gid) * TW;
                    bh[ni][0] = Bhs[nr + w0]; bh[ni][1] = Bhs[nr + w1];
                    bl[ni][0] = Bls[nr + w0]; bl[ni][1] = Bls[nr + w1];
                }
                #pragma unroll
                for (int mi = 0; mi < 4; mi++)
                    #pragma unroll
                    for (int ni = 0; ni < 4; ni++) {
                        mma_bf16(acc[mi][ni], ah[mi], bl[ni]);
                        mma_bf16(acc[mi][ni], al[mi], bh[ni]);
                        mma_bf16(acc[mi][ni], ah[mi], bh[ni]);
                    }
            }
        }
        if (ch + 1 < nChunks) {
            uint32_t* b0 = sm + ((ch + 1) & 1) * STAGEW;
            #pragma unroll
            for (int p = 0; p < 4; p++) {
                uint32_t h0, l0, h1, l1;
                bsplit(ra[p].x, ra[p].y, h0, l0);
                bsplit(ra[p].z, ra[p].w, h1, l1);
                *(uint2*)(b0 + soff[p])          = make_uint2(h0, h1);
                *(uint2*)(b0 + TILEW + soff[p])  = make_uint2(l0, l1);
                bsplit(rb[p].x, rb[p].y, h0, l0);
                bsplit(rb[p].z, rb[p].w, h1, l1);
                *(uint2*)(b0 + 2 * TILEW + soff[p]) = make_uint2(h0, h1);
                *(uint2*)(b0 + 3 * TILEW + soff[p]) = make_uint2(l0, l1);
            }
            __syncthreads();
        }
    }

    // ---- epilogue (identical to R7) ----
    #pragma unroll
    for (int mi = 0; mi < 4; mi++) {
        const int mr0 = m0 + wr * 64 + mi * 16 + gid;
        const int mr1 = mr0 + 8;
        float e0 = 0.f, e1 = 0.f, d0 = 0.f, d1 = 0.f;
        if (mode == M_OUT2) {
            e0 = g_ent[z][mr0]; e1 = g_ent[z][mr1];
            d0 = g_dep[z][mr0]; d1 = g_dep[z][mr1];
        }
        #pragma unroll
        for (int ni = 0; ni < 4; ni++) {
            const int nc = n0 + wc * 32 + ni * 8 + 2 * t4;
            float v00 = acc[mi][ni][0], v01 = acc[mi][ni][1];
            float v10 = acc[mi][ni][2], v11 = acc[mi][ni][3];
            if (mode == M_DIV) {
                v00 = 1.0f - v00; v01 = 1.0f - v01;
                v10 = 1.0f - v10; v11 = 1.0f - v11;
            } else if (mode == M_SIM) {
                v00 += g_AP[(size_t)mr0 * TB_ + nc];
                v01 += g_AP[(size_t)mr0 * TB_ + nc + 1];
                v10 += g_AP[(size_t)mr1 * TB_ + nc];
                v11 += g_AP[(size_t)mr1 * TB_ + nc + 1];
            }
            if (mode == M_OUT2) {
                const float we0 = g_w2e[nc], we1 = g_w2e[nc + 1];
                const float wd0 = g_w2d[nc], wd1 = g_w2d[nc + 1];
                float* y0 = g_y + (size_t)(bi * TB_ + mr0) * D_ + bj * WB_ + nc;
                float* y1 = g_y + (size_t)(bi * TB_ + mr1) * D_ + bj * WB_ + nc;
                y0[0] = v00 + e0 * we0 + d0 * wd0;
                y0[1] = v01 + e0 * we1 + d0 * wd1;
                y1[0] = v10 + e1 * we0 + d1 * wd0;
                y1[1] = v11 + e1 * we1 + d1 * wd1;
            } else {
                float* c0p = C + (size_t)mr0 * ldc + nc;
                float* c1p = C + (size_t)mr1 * ldc + nc;
                *(float2*)c0p = make_float2(v00, v01);
                *(float2*)c1p = make_float2(v10, v11);
            }
        }
    }
}

// ---------------- elementwise stage kernels (identical to R7) ----------------
__global__ void k_norm(const float* __restrict__ x) {
    int t = blockIdx.x, tid = threadIdx.x;
    const float* xp = x + (size_t)t * D_;
    float v = 0.0f;
    for (int j = tid; j < D_; j += 256) { float a = xp[j]; v += a * a; }
    v = blockReduce<false>(v);
    float inv = 1.0f / fmaxf(sqrtf(v), 1e-12f);
    for (int j = tid; j < D_; j += 256) g_xu[(size_t)t * D_ + j] = xp[j] * inv;
}

__global__ void k_ap() {
    int idx = blockIdx.x * 256 + threadIdx.x;
    int p = idx >> 10, c = idx & 1023;
    int ih = c >> 1;
    float ang = (float)p / powf(10000.0f, (2.0f * (float)ih) / 1024.0f);
    g_AP[idx] = (c & 1) ? cosf(ang) : sinf(ang);
}

__global__ void k_repack(const float* __restrict__ W2) {
    int idx = blockIdx.x * 256 + threadIdx.x;
    if (idx >= WB_ * (WB_ + 2)) return;
    int n = idx / (WB_ + 2), k = idx % (WB_ + 2);
    float v = W2[idx];
    if (k < WB_)       g_W2[n * WB_ + k] = v;
    else if (k == WB_) g_w2e[n] = v;
    else               g_w2d[n] = v;
}

__global__ void k_softmax() {
    int row = blockIdx.x;
    int b = row >> 10, q = row & 1023;
    int i = b >> 2;
    int tid = threadIdx.x;
    float* sp = g_attw[b] + (size_t)q * TB_;
    const float* dv = g_div[i] + (size_t)q * TB_;
    float s[4], d[4];
    #pragma unroll
    for (int j = 0; j < 4; j++) { s[j] = sp[tid + j * 256]; d[j] = dv[tid + j * 256]; }
    float mx = fmaxf(fmaxf(s[0], s[1]), fmaxf(s[2], s[3]));
    mx = blockReduce<true>(mx);
    float e[4], Z = 0.f, t = 0.f, ww = 0.f, ds = 0.f;
    #pragma unroll
    for (int j = 0; j < 4; j++) {
        e[j] = __expf(s[j] - mx);
        Z += e[j]; t += e[j] * (s[j] - mx); ww += d[j] * e[j]; ds += d[j];
    }
    Z = blockReduce<false>(Z);
    t = blockReduce<false>(t);
    ww = blockReduce<false>(ww);
    ds = blockReduce<false>(ds);
    float invZ = 1.0f / Z;
    #pragma unroll
    for (int j = 0; j < 4; j++) sp[tid + j * 256] = e[j] * invZ;
    if (tid == 0) {
        g_ent[b][q] = (logf(Z) - t * invZ) * (1.0f / 6.931471805599453f);
        g_dep[b][q] = (ww * invZ) / ds;
    }
}

__global__ void k_entnorm() {
    int b = blockIdx.x, tid = threadIdx.x;
    float v = 0.0f;
    for (int j = tid; j < TB_; j += 256) v += fabsf(g_ent[b][j]);
    v = blockReduce<false>(v);
    float inv = 1.0f / fmaxf(v, 1e-12f);
    for (int j = tid; j < TB_; j += 256) g_ent[b][j] *= inv;
}

// Vt[b][n][k] = V[(i*TB+k)*D + j*WB+n] * (1 + dep[b][k])
__global__ void k_vt() {
    __shared__ float tile[32][33];
    int b = blockIdx.z, i = b >> 2, j = b & 3;
    int k0 = blockIdx.x * 32, n0 = blockIdx.y * 32;
    int tx = threadIdx.x, ty = threadIdx.y;    // 32 x 8
    #pragma unroll
    for (int dy = 0; dy < 4; dy++) {
        int k = k0 + ty + dy * 8;
        int n = n0 + tx;
        tile[ty + dy * 8][tx] =
            g_V[(size_t)(i * TB_ + k) * D_ + j * WB_ + n] * (1.0f + g_dep[b][k]);
    }
    __syncthreads();
    #pragma unroll
    for (int dy = 0; dy < 4; dy++) {
        int n = n0 + ty + dy * 8;
        int k = k0 + tx;
        g_Vt[b][(size_t)n * TB_ + k] = tile[tx][ty + dy * 8];
    }
}

// ---------------- launch (identical to R7) -----------------------------------
extern "C" void kernel_launch(void* const* d_in, const int* in_sizes, int n_in,
                              void* d_out, int out_size) {
    const float* x    = (const float*)d_in[0];
    const float* Wq   = (const float*)d_in[1];
    const float* Wk   = (const float*)d_in[2];
    const float* Wv   = (const float*)d_in[3];
    const float* Wout = (const float*)d_in[4];
    const float* W2   = (const float*)d_in[5];
    float* out = (float*)d_out;

    cudaFuncSetAttribute(k_mma, cudaFuncAttributeMaxDynamicSharedMemorySize, SMEM_DYN);

    k_norm<<<T_, 256>>>(x);
    k_ap<<<(TB_ * TB_) / 256, 256>>>();
    k_repack<<<(WB_ * (WB_ + 2) + 255) / 256, 256>>>(W2);

    k_mma<<<dim3(TB_ / NT, TB_ / MT, S_), THREADS, SMEM_DYN>>>(M_DIV, nullptr, nullptr, nullptr);

    k_mma<<<dim3(D_ / NT, T_ / MT, 1), THREADS, SMEM_DYN>>>(M_Q, x, Wq, nullptr);
    k_mma<<<dim3(D_ / NT, T_ / MT, 1), THREADS, SMEM_DYN>>>(M_K, x, Wk, nullptr);
    k_mma<<<dim3(D_ / NT, T_ / MT, 1), THREADS, SMEM_DYN>>>(M_V, x, Wv, nullptr);

    k_mma<<<dim3(TB_ / NT, TB_ / MT, NB_), THREADS, SMEM_DYN>>>(M_SIM, nullptr, nullptr, nullptr);

    k_softmax<<<NB_ * TB_, 256>>>();
    k_entnorm<<<NB_, 256>>>();
    k_vt<<<dim3(TB_ / 32, WB_ / 32, NB_), dim3(32, 8)>>>();

    k_mma<<<dim3(WB_ / NT, TB_ / MT, NB_), THREADS, SMEM_DYN>>>(M_CTX, nullptr, nullptr, nullptr);
    k_mma<<<dim3(WB_ / NT, TB_ / MT, NB_), THREADS, SMEM_DYN>>>(M_OUT2, nullptr, nullptr, nullptr);
    k_mma<<<dim3(D_ / NT, T_ / MT, 1), THREADS, SMEM_DYN>>>(M_FIN, nullptr, Wout, out);
}